// round 4
// baseline (speedup 1.0000x reference)
#include <cuda_runtime.h>
#include <math.h>

// ---------------------------------------------------------------------------
// bilinear_attention: out = softmax(y @ (x @ Wb^T)^T, axis=Lx) @ x
// B=8, Lx=Ly=2048, D=512, all fp32.
// Round 1: pure fp32 pipeline (correctness + profiling baseline):
//   K1: g_xw = x @ Wb^T            (NT sgemm, M=16384, N=512, K=512)
//   K2: g_s  = y @ g_xw^T          (batched NT sgemm, 8 x [2048,2048,512])
//   K3: row softmax over g_s       (in-place, 16384 rows of 2048)
//   K4: out  = g_s @ x             (batched NN sgemm, 8 x [2048,512,2048])
// ---------------------------------------------------------------------------

#define BDIM   8
#define LX     2048
#define LY     2048
#define DDIM   512

// scratch (device globals: no allocation allowed)
__device__ float g_xw[(size_t)BDIM * LX * DDIM];                 // 32 MiB
__device__ float g_s [(size_t)BDIM * (size_t)LY * (size_t)LX];   // 128 MiB

#define BM 128
#define BN 128
#define BK 16
#define TM 8
#define TN 8
// threads = (BM/TM)*(BN/TN) = 256

// C[M,N] = A[M,K] * B[N,K]^T   (both operands K-contiguous, row-major)
__global__ __launch_bounds__(256)
void sgemm_nt(const float* __restrict__ A, const float* __restrict__ B,
              float* __restrict__ C, int M, int N, int K,
              long long strideA, long long strideB, long long strideC)
{
    int b = blockIdx.z;
    A += (long long)b * strideA;
    B += (long long)b * strideB;
    C += (long long)b * strideC;

    __shared__ float As[BK][BM];
    __shared__ float Bs[BK][BN];

    const int tid = threadIdx.x;
    const int tx  = tid % (BN / TN);   // 0..15 (N dir)
    const int ty  = tid / (BN / TN);   // 0..15 (M dir)
    const int rowBase = blockIdx.y * BM;
    const int colBase = blockIdx.x * BN;

    float acc[TM][TN];
#pragma unroll
    for (int i = 0; i < TM; i++)
#pragma unroll
        for (int j = 0; j < TN; j++) acc[i][j] = 0.0f;

    for (int k0 = 0; k0 < K; k0 += BK) {
        // load A tile [BM x BK], scatter transposed into As[k][m]
#pragma unroll
        for (int i = 0; i < (BM * BK) / (256 * 4); ++i) {       // 2 iters
            int idx = (tid + i * 256) * 4;
            int m   = idx / BK;
            int kk  = idx % BK;
            float4 v = *reinterpret_cast<const float4*>(
                &A[(long long)(rowBase + m) * K + k0 + kk]);
            As[kk + 0][m] = v.x; As[kk + 1][m] = v.y;
            As[kk + 2][m] = v.z; As[kk + 3][m] = v.w;
        }
        // load B tile [BN x BK], scatter transposed into Bs[k][n]
#pragma unroll
        for (int i = 0; i < (BN * BK) / (256 * 4); ++i) {       // 2 iters
            int idx = (tid + i * 256) * 4;
            int n   = idx / BK;
            int kk  = idx % BK;
            float4 v = *reinterpret_cast<const float4*>(
                &B[(long long)(colBase + n) * K + k0 + kk]);
            Bs[kk + 0][n] = v.x; Bs[kk + 1][n] = v.y;
            Bs[kk + 2][n] = v.z; Bs[kk + 3][n] = v.w;
        }
        __syncthreads();

#pragma unroll
        for (int kk = 0; kk < BK; ++kk) {
            float a[TM], bb[TN];
#pragma unroll
            for (int i = 0; i < TM; i++) a[i] = As[kk][ty * TM + i];
#pragma unroll
            for (int j = 0; j < TN; j++) bb[j] = Bs[kk][tx * TN + j];
#pragma unroll
            for (int i = 0; i < TM; i++)
#pragma unroll
                for (int j = 0; j < TN; j++)
                    acc[i][j] += a[i] * bb[j];
        }
        __syncthreads();
    }

#pragma unroll
    for (int i = 0; i < TM; i++) {
        long long m = rowBase + ty * TM + i;
#pragma unroll
        for (int j = 0; j < TN; j += 4) {
            float4 v = make_float4(acc[i][j], acc[i][j + 1],
                                   acc[i][j + 2], acc[i][j + 3]);
            *reinterpret_cast<float4*>(&C[m * N + colBase + tx * TN + j]) = v;
        }
    }
}

// C[M,N] = A[M,K] * B[K,N]   (A K-contiguous, B N-contiguous)
__global__ __launch_bounds__(256)
void sgemm_nn(const float* __restrict__ A, const float* __restrict__ B,
              float* __restrict__ C, int M, int N, int K,
              long long strideA, long long strideB, long long strideC)
{
    int b = blockIdx.z;
    A += (long long)b * strideA;
    B += (long long)b * strideB;
    C += (long long)b * strideC;

    __shared__ float As[BK][BM];
    __shared__ float Bs[BK][BN];

    const int tid = threadIdx.x;
    const int tx  = tid % (BN / TN);
    const int ty  = tid / (BN / TN);
    const int rowBase = blockIdx.y * BM;
    const int colBase = blockIdx.x * BN;

    float acc[TM][TN];
#pragma unroll
    for (int i = 0; i < TM; i++)
#pragma unroll
        for (int j = 0; j < TN; j++) acc[i][j] = 0.0f;

    for (int k0 = 0; k0 < K; k0 += BK) {
#pragma unroll
        for (int i = 0; i < (BM * BK) / (256 * 4); ++i) {
            int idx = (tid + i * 256) * 4;
            int m   = idx / BK;
            int kk  = idx % BK;
            float4 v = *reinterpret_cast<const float4*>(
                &A[(long long)(rowBase + m) * K + k0 + kk]);
            As[kk + 0][m] = v.x; As[kk + 1][m] = v.y;
            As[kk + 2][m] = v.z; As[kk + 3][m] = v.w;
        }
        // B tile [BK x BN], contiguous in n
#pragma unroll
        for (int i = 0; i < (BK * BN) / (256 * 4); ++i) {
            int idx = (tid + i * 256) * 4;
            int kk  = idx / BN;
            int n   = idx % BN;
            float4 v = *reinterpret_cast<const float4*>(
                &B[(long long)(k0 + kk) * N + colBase + n]);
            *reinterpret_cast<float4*>(&Bs[kk][n]) = v;
        }
        __syncthreads();

#pragma unroll
        for (int kk = 0; kk < BK; ++kk) {
            float a[TM], bb[TN];
#pragma unroll
            for (int i = 0; i < TM; i++) a[i] = As[kk][ty * TM + i];
#pragma unroll
            for (int j = 0; j < TN; j++) bb[j] = Bs[kk][tx * TN + j];
#pragma unroll
            for (int i = 0; i < TM; i++)
#pragma unroll
                for (int j = 0; j < TN; j++)
                    acc[i][j] += a[i] * bb[j];
        }
        __syncthreads();
    }

#pragma unroll
    for (int i = 0; i < TM; i++) {
        long long m = rowBase + ty * TM + i;
#pragma unroll
        for (int j = 0; j < TN; j += 4) {
            float4 v = make_float4(acc[i][j], acc[i][j + 1],
                                   acc[i][j + 2], acc[i][j + 3]);
            *reinterpret_cast<float4*>(&C[m * N + colBase + tx * TN + j]) = v;
        }
    }
}

// in-place row softmax; one block per row of LX=2048, 256 threads, 8 elems/thread
__global__ __launch_bounds__(256)
void softmax_rows(float* __restrict__ S)
{
    const int N = LX;
    long long row = blockIdx.x;
    float* p = S + row * (long long)N;
    int tid = threadIdx.x;

    float4 v0 = reinterpret_cast<float4*>(p)[tid];
    float4 v1 = reinterpret_cast<float4*>(p)[tid + 256];

    float m = fmaxf(fmaxf(fmaxf(v0.x, v0.y), fmaxf(v0.z, v0.w)),
                    fmaxf(fmaxf(v1.x, v1.y), fmaxf(v1.z, v1.w)));
#pragma unroll
    for (int o = 16; o > 0; o >>= 1)
        m = fmaxf(m, __shfl_xor_sync(0xffffffffu, m, o));

    __shared__ float red[8];
    if ((tid & 31) == 0) red[tid >> 5] = m;
    __syncthreads();
    float mm = red[0];
#pragma unroll
    for (int i = 1; i < 8; i++) mm = fmaxf(mm, red[i]);
    __syncthreads();

    v0.x = expf(v0.x - mm); v0.y = expf(v0.y - mm);
    v0.z = expf(v0.z - mm); v0.w = expf(v0.w - mm);
    v1.x = expf(v1.x - mm); v1.y = expf(v1.y - mm);
    v1.z = expf(v1.z - mm); v1.w = expf(v1.w - mm);

    float s = (v0.x + v0.y + v0.z + v0.w) + (v1.x + v1.y + v1.z + v1.w);
#pragma unroll
    for (int o = 16; o > 0; o >>= 1)
        s += __shfl_xor_sync(0xffffffffu, s, o);
    if ((tid & 31) == 0) red[tid >> 5] = s;
    __syncthreads();
    float total = 0.0f;
#pragma unroll
    for (int i = 0; i < 8; i++) total += red[i];
    float inv = 1.0f / total;

    v0.x *= inv; v0.y *= inv; v0.z *= inv; v0.w *= inv;
    v1.x *= inv; v1.y *= inv; v1.z *= inv; v1.w *= inv;

    reinterpret_cast<float4*>(p)[tid]       = v0;
    reinterpret_cast<float4*>(p)[tid + 256] = v1;
}

extern "C" void kernel_launch(void* const* d_in, const int* in_sizes, int n_in,
                              void* d_out, int out_size)
{
    const float* x  = (const float*)d_in[0];   // [B, Lx, D]
    const float* y  = (const float*)d_in[1];   // [B, Ly, D]
    const float* Wb = (const float*)d_in[2];   // [D, D]
    float* out = (float*)d_out;                // [B, Ly, D]

    float* xw = nullptr;
    float* s  = nullptr;
    cudaGetSymbolAddress((void**)&xw, g_xw);
    cudaGetSymbolAddress((void**)&s,  g_s);

    // K1: xw = x @ Wb^T   (NT, M = B*Lx = 16384, N = D = 512, K = D = 512)
    {
        dim3 grid(DDIM / BN, (BDIM * LX) / BM, 1);   // (4, 128, 1)
        sgemm_nt<<<grid, 256>>>(x, Wb, xw,
                                BDIM * LX, DDIM, DDIM, 0, 0, 0);
    }

    // K2: s[b] = y[b] @ xw[b]^T  (batched NT, M=Ly, N=Lx, K=D)
    {
        dim3 grid(LX / BN, LY / BM, BDIM);           // (16, 16, 8)
        sgemm_nt<<<grid, 256>>>(y, xw, s,
                                LY, LX, DDIM,
                                (long long)LY * DDIM,
                                (long long)LX * DDIM,
                                (long long)LY * LX);
    }

    // K3: softmax over Lx for each of B*Ly rows
    {
        softmax_rows<<<BDIM * LY, 256>>>(s);
    }

    // K4: out[b] = s[b] @ x[b]  (batched NN, M=Ly, N=D, K=Lx)
    {
        dim3 grid(DDIM / BN, LY / BM, BDIM);         // (4, 16, 8)
        sgemm_nn<<<grid, 256>>>(s, x, out,
                                LY, DDIM, LX,
                                (long long)LY * LX,
                                (long long)LX * DDIM,
                                (long long)LY * DDIM);
    }
}

// round 8
// speedup vs baseline: 2.9522x; 2.9522x over previous
#include <cuda_runtime.h>
#include <cstdint>
#include <math.h>

// ---------------------------------------------------------------------------
// bilinear_attention: out = softmax(y @ (x @ Wb^T)^T, axis=Lx) @ x
// B=8, Lx=Ly=2048, D=512, fp32 io.
// Round 5: tcgen05 3xTF32 GEMMs, arch-feature-guarded so the compute_103
// (non-'a') compilation pass compiles an FFMA fallback instead of dying.
//   K1: xw = x @ Wb^T        (3xTF32 NT, M=16384,N=512,K=512)
//   T : xt = transpose(x)    per batch  [D, Lx]
//   K2: s  = y @ xw^T        (batched 3xTF32 NT, 8 x [2048,2048,512])
//   K3: softmax rows of s
//   K4: out= s @ xt^T        (batched 3xTF32 NT, 8 x [2048,512,2048])
// ---------------------------------------------------------------------------

#define BDIM   8
#define LX     2048
#define LY     2048
#define DDIM   512

__device__ float g_xw[(size_t)BDIM * LX * DDIM];                 // 32 MiB
__device__ float g_s [(size_t)BDIM * (size_t)LY * (size_t)LX];   // 128 MiB
__device__ float g_xt[(size_t)BDIM * DDIM * LX];                 // 32 MiB

// ---- does this compilation pass support tcgen05? --------------------------
#if defined(__CUDA_ARCH__)
#  if defined(__CUDA_ARCH_FEAT_SM103_ALL) || defined(__CUDA_ARCH_FEAT_SM100_ALL) \
      || (defined(__CUDA_ARCH_SPECIFIC__) && (__CUDA_ARCH_SPECIFIC__ >= 1000))   \
      || (defined(__CUDA_ARCH_FAMILY_SPECIFIC__) && (__CUDA_ARCH_FAMILY_SPECIFIC__ >= 1000))
#    define HAS_TCGEN05 1
#  else
#    define HAS_TCGEN05 0
#  endif
#else
#  define HAS_TCGEN05 0
#endif

// ============================ PTX helpers ==================================
__device__ __forceinline__ uint32_t smem_u32(const void* p) {
    uint32_t a;
    asm("{ .reg .u64 t; cvta.to.shared.u64 t, %1; cvt.u32.u64 %0, t; }"
        : "=r"(a) : "l"(p));
    return a;
}

#if HAS_TCGEN05
__device__ __forceinline__ uint32_t elect_one() {
    uint32_t p;
    asm volatile("{\n .reg .pred p;\n elect.sync _|p, 0xFFFFFFFF;\n"
                 " selp.b32 %0, 1, 0, p;\n}" : "=r"(p));
    return p;
}

#define TCGEN05_ALLOC(smem_addr, nCols) \
    asm volatile("tcgen05.alloc.cta_group::1.sync.aligned.shared::cta.b32 [%0], %1;" \
                 :: "r"((uint32_t)(smem_addr)), "r"((uint32_t)(nCols)) : "memory")
#define TCGEN05_DEALLOC(tmem_addr, nCols) \
    asm volatile("tcgen05.dealloc.cta_group::1.sync.aligned.b32 %0, %1;" \
                 :: "r"(tmem_addr), "r"((uint32_t)(nCols)))
#define TCGEN05_RELINQUISH() \
    asm volatile("tcgen05.relinquish_alloc_permit.cta_group::1.sync.aligned;")
#define TCGEN05_COMMIT(mbar) \
    asm volatile("tcgen05.commit.cta_group::1.mbarrier::arrive::one.shared::cluster.b64 [%0];" \
                 :: "r"((uint32_t)(mbar)) : "memory")
#define TCGEN05_FENCE_AFTER() \
    asm volatile("tcgen05.fence::after_thread_sync;" ::: "memory")
#define TCGEN05_FENCE_BEFORE() \
    asm volatile("tcgen05.fence::before_thread_sync;" ::: "memory")
#define TCGEN05_WAIT_LD() \
    asm volatile("tcgen05.wait::ld.sync.aligned;" ::: "memory")
#define FENCE_PROXY_ASYNC() \
    asm volatile("fence.proxy.async.shared::cta;" ::: "memory")

#define MBARRIER_INIT(mbar, cnt) \
    asm volatile("mbarrier.init.shared.b64 [%0], %1;" \
                 :: "r"((uint32_t)(mbar)), "r"((uint32_t)(cnt)) : "memory")
#define MBARRIER_INVAL(mbar) \
    asm volatile("mbarrier.inval.shared.b64 [%0];" :: "r"((uint32_t)(mbar)) : "memory")

#define MBARRIER_WAIT_PARITY(mbar_addr, phase_parity) do {                       \
    uint32_t _mbar = (uint32_t)(mbar_addr);                                      \
    uint32_t _par  = (uint32_t)(phase_parity);                                   \
    uint32_t _done;                                                              \
    asm volatile("{\n .reg .pred p;\n"                                           \
        " mbarrier.try_wait.parity.acquire.cta.shared::cta.b64 p, [%1], %2;\n"   \
        " selp.b32 %0, 1, 0, p;\n}"                                              \
        : "=r"(_done) : "r"(_mbar), "r"(_par) : "memory");                       \
    if (!_done) {                                                                \
        asm volatile("{\n .reg .pred P1;\n"                                      \
            "WL_%=:\n"                                                           \
            " mbarrier.try_wait.parity.acquire.cta.shared::cta.b64 P1, [%0], %1, 0x989680;\n" \
            " @P1 bra.uni WD_%=;\n"                                              \
            " bra.uni WL_%=;\n"                                                  \
            "WD_%=:\n}"                                                          \
            :: "r"(_mbar), "r"(_par) : "memory");                                \
    }                                                                            \
} while (0)

#define TCGEN05_LD_32X32B_X32(r, tmem_addr) \
    asm volatile( \
        "tcgen05.ld.sync.aligned.32x32b.x32.b32 " \
        "{%0, %1, %2, %3, %4, %5, %6, %7, " \
        " %8, %9, %10, %11, %12, %13, %14, %15, " \
        " %16, %17, %18, %19, %20, %21, %22, %23, " \
        " %24, %25, %26, %27, %28, %29, %30, %31}, [%32];" \
        : "=r"((r)[0]),  "=r"((r)[1]),  "=r"((r)[2]),  "=r"((r)[3]), \
          "=r"((r)[4]),  "=r"((r)[5]),  "=r"((r)[6]),  "=r"((r)[7]), \
          "=r"((r)[8]),  "=r"((r)[9]),  "=r"((r)[10]), "=r"((r)[11]), \
          "=r"((r)[12]), "=r"((r)[13]), "=r"((r)[14]), "=r"((r)[15]), \
          "=r"((r)[16]), "=r"((r)[17]), "=r"((r)[18]), "=r"((r)[19]), \
          "=r"((r)[20]), "=r"((r)[21]), "=r"((r)[22]), "=r"((r)[23]), \
          "=r"((r)[24]), "=r"((r)[25]), "=r"((r)[26]), "=r"((r)[27]), \
          "=r"((r)[28]), "=r"((r)[29]), "=r"((r)[30]), "=r"((r)[31]) \
        : "r"(tmem_addr))

// SW128 K-major smem descriptor: layout=2, version=1, SBO=64, LBO=1
static constexpr uint64_t DESC_BASE =
    (uint64_t(2) << 61) | (uint64_t(1) << 46) | (uint64_t(64) << 32) | (uint64_t(1) << 16);
__device__ __forceinline__ uint64_t make_desc(uint32_t addr) {
    return DESC_BASE | ((uint64_t)(addr >> 4) & 0x3FFF);
}

// tcgen05.mma kind::tf32, SS form (both operands via smem descriptor)
__device__ __forceinline__ void mma_tf32_ss(uint32_t d, uint64_t ad, uint64_t bd,
                                            uint32_t idesc, uint32_t enable) {
    asm volatile(
        "{\n .reg .pred p;\n setp.ne.u32 p, %4, 0;\n"
        " tcgen05.mma.cta_group::1.kind::tf32 [%0], %1, %2, %3, p;\n}"
        :: "r"(d), "l"(ad), "l"(bd), "r"(idesc), "r"(enable) : "memory");
}
#endif  // HAS_TCGEN05

__device__ __forceinline__ float tf32_hi(float v) {
    uint32_t u;
    asm("cvt.rna.tf32.f32 %0, %1;" : "=r"(u) : "f"(v));
    return __uint_as_float(u);
}

// ======================= 3xTF32 NT GEMM ====================================
// C[M,N] = A[M,K] * B[N,K]^T, fp32 in/out, split-precision via tf32 hi/lo.
// CTA tile 128x128, K-tile 32 (= one 128B SW128 row; 4 k-steps of K=8).
#define GMT 128
#define GNT 128
#define GKT 32
#define PLANE    16384          // 128 rows * 128B
#define STAGEB   (4 * PLANE)    // Ahi, Alo, Bhi, Blo
#define GEMM_SMEM (2048 + 2 * STAGEB)

#if HAS_TCGEN05
// idesc: dtype F32(1<<4), atype TF32(2<<7), btype TF32(2<<10), N/8<<17, M/16<<24
static constexpr uint32_t IDESC_TF32 =
    (1u << 4) | (2u << 7) | (2u << 10) | ((GNT / 8) << 17) | ((GMT / 16) << 24);
#endif

__global__ __launch_bounds__(256, 1)
void gemm3xtf32_nt(const float* __restrict__ A, const float* __restrict__ B,
                   float* __restrict__ C, int M, int N, int K,
                   long long sA, long long sB, long long sC)
{
    extern __shared__ char smem[];
    const int tid = threadIdx.x;
    const int bz  = blockIdx.z;
    A += (long long)bz * sA;
    B += (long long)bz * sB;
    C += (long long)bz * sC;
    const int rowBase = blockIdx.y * GMT;
    const int colBase = blockIdx.x * GNT;

#if HAS_TCGEN05
    // ======================= tcgen05 path ==================================
    const uint32_t base = smem_u32(smem);
    const uint32_t tb   = (base + 32 + 1023) & ~1023u;   // shared-space tile base
    char* tgen = smem + (tb - base);                     // generic-space tile base
    const int wid = tid >> 5, lid = tid & 31;

    if (wid == 0) {
        TCGEN05_ALLOC(base + 0, 128);
        TCGEN05_RELINQUISH();
    }
    if (tid == 0) MBARRIER_INIT(base + 16, 1);
    __syncthreads();
    uint32_t tmem;
    asm volatile("ld.shared.b32 %0, [%1];" : "=r"(tmem) : "r"(base + 0));

    // per-thread load map: 1024 16B-chunks per plane-side, 4 per thread
    int r_[4]; int c4_[4]; uint32_t so_[4];
#pragma unroll
    for (int i = 0; i < 4; i++) {
        int ch = tid + i * 256;
        int r  = ch >> 3, c = ch & 7;
        r_[i] = r; c4_[i] = c * 4;
        uint32_t bo = (uint32_t)(r * 128 + c * 16);
        so_[i] = bo ^ ((bo >> 3) & 0x70);               // SW128 swizzle
    }
    const float* Ap[4]; const float* Bp[4];
#pragma unroll
    for (int i = 0; i < 4; i++) {
        Ap[i] = A + (long long)(rowBase + r_[i]) * K + c4_[i];
        Bp[i] = B + (long long)(colBase + r_[i]) * K + c4_[i];
    }

    const int NKT = K / GKT;
    float4 ra[4], rb[4];

    // prologue: tile 0 -> stage 0
#pragma unroll
    for (int i = 0; i < 4; i++) { ra[i] = *(const float4*)(Ap[i]); rb[i] = *(const float4*)(Bp[i]); }
    {
        char* st = tgen;
#pragma unroll
        for (int i = 0; i < 4; i++) {
            float4 h, l;
            h.x = tf32_hi(ra[i].x); l.x = ra[i].x - h.x;
            h.y = tf32_hi(ra[i].y); l.y = ra[i].y - h.y;
            h.z = tf32_hi(ra[i].z); l.z = ra[i].z - h.z;
            h.w = tf32_hi(ra[i].w); l.w = ra[i].w - h.w;
            *(float4*)(st + so_[i])             = h;
            *(float4*)(st + PLANE + so_[i])     = l;
            h.x = tf32_hi(rb[i].x); l.x = rb[i].x - h.x;
            h.y = tf32_hi(rb[i].y); l.y = rb[i].y - h.y;
            h.z = tf32_hi(rb[i].z); l.z = rb[i].z - h.z;
            h.w = tf32_hi(rb[i].w); l.w = rb[i].w - h.w;
            *(float4*)(st + 2 * PLANE + so_[i]) = h;
            *(float4*)(st + 3 * PLANE + so_[i]) = l;
        }
    }
    __syncthreads();

    for (int kt = 0; kt < NKT; ++kt) {
        const int cur = kt & 1;
        const bool more = (kt + 1 < NKT);
        // prefetch next tile into registers (overlaps with MMA wait)
        if (more) {
            const int k0 = (kt + 1) * GKT;
#pragma unroll
            for (int i = 0; i < 4; i++) {
                ra[i] = *(const float4*)(Ap[i] + k0);
                rb[i] = *(const float4*)(Bp[i] + k0);
            }
        }
        // issue MMAs on current stage (warp 0)
        if (wid == 0) {
            FENCE_PROXY_ASYNC();
            if (elect_one()) {
                const uint32_t sa = tb + cur * STAGEB;
                const uint64_t ah = make_desc(sa);
                const uint64_t al = make_desc(sa + PLANE);
                const uint64_t bh = make_desc(sa + 2 * PLANE);
                const uint64_t bl = make_desc(sa + 3 * PLANE);
#pragma unroll
                for (int ks = 0; ks < 4; ks++) {
                    const uint64_t ko = (uint64_t)(ks * 2);   // 32B per k-step
                    mma_tf32_ss(tmem, ah + ko, bh + ko, IDESC_TF32,
                                (kt == 0 && ks == 0) ? 0u : 1u);
                    mma_tf32_ss(tmem, ah + ko, bl + ko, IDESC_TF32, 1u);
                    mma_tf32_ss(tmem, al + ko, bh + ko, IDESC_TF32, 1u);
                }
                TCGEN05_COMMIT(base + 16);
            }
        }
        // store next tile into other stage while MMAs run
        if (more) {
            char* st = tgen + (1 - cur) * STAGEB;
#pragma unroll
            for (int i = 0; i < 4; i++) {
                float4 h, l;
                h.x = tf32_hi(ra[i].x); l.x = ra[i].x - h.x;
                h.y = tf32_hi(ra[i].y); l.y = ra[i].y - h.y;
                h.z = tf32_hi(ra[i].z); l.z = ra[i].z - h.z;
                h.w = tf32_hi(ra[i].w); l.w = ra[i].w - h.w;
                *(float4*)(st + so_[i])             = h;
                *(float4*)(st + PLANE + so_[i])     = l;
                h.x = tf32_hi(rb[i].x); l.x = rb[i].x - h.x;
                h.y = tf32_hi(rb[i].y); l.y = rb[i].y - h.y;
                h.z = tf32_hi(rb[i].z); l.z = rb[i].z - h.z;
                h.w = tf32_hi(rb[i].w); l.w = rb[i].w - h.w;
                *(float4*)(st + 2 * PLANE + so_[i]) = h;
                *(float4*)(st + 3 * PLANE + so_[i]) = l;
            }
        }
        __syncthreads();
        MBARRIER_WAIT_PARITY(base + 16, kt & 1);
    }

    TCGEN05_FENCE_AFTER();
    // epilogue: warps 0-3 read D (128 lanes x 128 fp32 cols) and store
    if (wid < 4) {
        const long long m = rowBase + wid * 32 + lid;
#pragma unroll
        for (int chunk = 0; chunk < 4; chunk++) {
            uint32_t d[32];
            TCGEN05_LD_32X32B_X32(d, tmem + chunk * 32);
            TCGEN05_WAIT_LD();
            float4* dst = (float4*)&C[m * (long long)N + colBase + chunk * 32];
#pragma unroll
            for (int j = 0; j < 8; j++) {
                dst[j] = make_float4(__uint_as_float(d[4 * j + 0]),
                                     __uint_as_float(d[4 * j + 1]),
                                     __uint_as_float(d[4 * j + 2]),
                                     __uint_as_float(d[4 * j + 3]));
            }
        }
        TCGEN05_FENCE_BEFORE();
    }
    __syncthreads();
    if (tid == 0) MBARRIER_INVAL(base + 16);
    __syncthreads();
    if (wid == 0) {
        TCGEN05_DEALLOC(tmem, 128);
    }

#else
    // ================== FFMA fallback (compute_103 pass) ===================
    // Register-tiled SGEMM NT, As/Bs carved from dynamic smem.
    const int BKf = 16, TMf = 8, TNf = 8;
    float* As = (float*)smem;                         // [BKf][GMT]
    float* Bs = (float*)(smem + BKf * GMT * 4);       // [BKf][GNT]

    const int tx = tid % (GNT / TNf);                 // 0..15
    const int ty = tid / (GNT / TNf);                 // 0..15

    float acc[TMf][TNf];
#pragma unroll
    for (int i = 0; i < TMf; i++)
#pragma unroll
        for (int j = 0; j < TNf; j++) acc[i][j] = 0.0f;

    for (int k0 = 0; k0 < K; k0 += BKf) {
#pragma unroll
        for (int i = 0; i < (GMT * BKf) / (256 * 4); ++i) {
            int idx = (tid + i * 256) * 4;
            int m = idx / BKf, kk = idx % BKf;
            float4 v = *reinterpret_cast<const float4*>(
                &A[(long long)(rowBase + m) * K + k0 + kk]);
            As[(kk + 0) * GMT + m] = v.x; As[(kk + 1) * GMT + m] = v.y;
            As[(kk + 2) * GMT + m] = v.z; As[(kk + 3) * GMT + m] = v.w;
        }
#pragma unroll
        for (int i = 0; i < (GNT * BKf) / (256 * 4); ++i) {
            int idx = (tid + i * 256) * 4;
            int n = idx / BKf, kk = idx % BKf;
            float4 v = *reinterpret_cast<const float4*>(
                &B[(long long)(colBase + n) * K + k0 + kk]);
            Bs[(kk + 0) * GNT + n] = v.x; Bs[(kk + 1) * GNT + n] = v.y;
            Bs[(kk + 2) * GNT + n] = v.z; Bs[(kk + 3) * GNT + n] = v.w;
        }
        __syncthreads();
#pragma unroll
        for (int kk = 0; kk < BKf; ++kk) {
            float a[TMf], bb[TNf];
#pragma unroll
            for (int i = 0; i < TMf; i++) a[i] = As[kk * GMT + ty * TMf + i];
#pragma unroll
            for (int j = 0; j < TNf; j++) bb[j] = Bs[kk * GNT + tx * TNf + j];
#pragma unroll
            for (int i = 0; i < TMf; i++)
#pragma unroll
                for (int j = 0; j < TNf; j++) acc[i][j] += a[i] * bb[j];
        }
        __syncthreads();
    }
#pragma unroll
    for (int i = 0; i < TMf; i++) {
        long long m = rowBase + ty * TMf + i;
#pragma unroll
        for (int j = 0; j < TNf; j += 4) {
            float4 v = make_float4(acc[i][j], acc[i][j + 1],
                                   acc[i][j + 2], acc[i][j + 3]);
            *reinterpret_cast<float4*>(&C[m * (long long)N + colBase + tx * TNf + j]) = v;
        }
    }
#endif
}

// ===================== transpose: xt[b][d][l] = x[b][l][d] =================
__global__ __launch_bounds__(256)
void transpose_x(const float* __restrict__ x, float* __restrict__ xt)
{
    __shared__ float t[32][33];
    const int b  = blockIdx.z;
    const int l0 = blockIdx.x * 32;
    const int d0 = blockIdx.y * 32;
    const float* xb = x + (long long)b * LX * DDIM;
    float* xtb = xt + (long long)b * DDIM * LX;
    const int tx = threadIdx.x, ty = threadIdx.y;   // 32 x 8
#pragma unroll
    for (int i = 0; i < 32; i += 8)
        t[ty + i][tx] = xb[(long long)(l0 + ty + i) * DDIM + d0 + tx];
    __syncthreads();
#pragma unroll
    for (int i = 0; i < 32; i += 8)
        xtb[(long long)(d0 + ty + i) * LX + l0 + tx] = t[tx][ty + i];
}

// ========================== row softmax ====================================
__global__ __launch_bounds__(256)
void softmax_rows(float* __restrict__ S)
{
    const int N = LX;
    long long row = blockIdx.x;
    float* p = S + row * (long long)N;
    int tid = threadIdx.x;

    float4 v0 = reinterpret_cast<float4*>(p)[tid];
    float4 v1 = reinterpret_cast<float4*>(p)[tid + 256];

    float m = fmaxf(fmaxf(fmaxf(v0.x, v0.y), fmaxf(v0.z, v0.w)),
                    fmaxf(fmaxf(v1.x, v1.y), fmaxf(v1.z, v1.w)));
#pragma unroll
    for (int o = 16; o > 0; o >>= 1)
        m = fmaxf(m, __shfl_xor_sync(0xffffffffu, m, o));

    __shared__ float red[8];
    if ((tid & 31) == 0) red[tid >> 5] = m;
    __syncthreads();
    float mm = red[0];
#pragma unroll
    for (int i = 1; i < 8; i++) mm = fmaxf(mm, red[i]);
    __syncthreads();

    v0.x = expf(v0.x - mm); v0.y = expf(v0.y - mm);
    v0.z = expf(v0.z - mm); v0.w = expf(v0.w - mm);
    v1.x = expf(v1.x - mm); v1.y = expf(v1.y - mm);
    v1.z = expf(v1.z - mm); v1.w = expf(v1.w - mm);

    float s = (v0.x + v0.y + v0.z + v0.w) + (v1.x + v1.y + v1.z + v1.w);
#pragma unroll
    for (int o = 16; o > 0; o >>= 1)
        s += __shfl_xor_sync(0xffffffffu, s, o);
    if ((tid & 31) == 0) red[tid >> 5] = s;
    __syncthreads();
    float total = 0.0f;
#pragma unroll
    for (int i = 0; i < 8; i++) total += red[i];
    float inv = 1.0f / total;

    v0.x *= inv; v0.y *= inv; v0.z *= inv; v0.w *= inv;
    v1.x *= inv; v1.y *= inv; v1.z *= inv; v1.w *= inv;

    reinterpret_cast<float4*>(p)[tid]       = v0;
    reinterpret_cast<float4*>(p)[tid + 256] = v1;
}

// =============================== launch ====================================
extern "C" void kernel_launch(void* const* d_in, const int* in_sizes, int n_in,
                              void* d_out, int out_size)
{
    const float* x  = (const float*)d_in[0];   // [B, Lx, D]
    const float* y  = (const float*)d_in[1];   // [B, Ly, D]
    const float* Wb = (const float*)d_in[2];   // [D, D]
    float* out = (float*)d_out;                // [B, Ly, D]

    float *xw = nullptr, *s = nullptr, *xt = nullptr;
    cudaGetSymbolAddress((void**)&xw, g_xw);
    cudaGetSymbolAddress((void**)&s,  g_s);
    cudaGetSymbolAddress((void**)&xt, g_xt);

    cudaFuncSetAttribute(gemm3xtf32_nt,
                         cudaFuncAttributeMaxDynamicSharedMemorySize, GEMM_SMEM);

    // K1: xw = x @ Wb^T (M=B*Lx=16384, N=512, K=512)
    {
        dim3 grid(DDIM / GNT, (BDIM * LX) / GMT, 1);     // (4, 128, 1)
        gemm3xtf32_nt<<<grid, 256, GEMM_SMEM>>>(x, Wb, xw,
                                                BDIM * LX, DDIM, DDIM, 0, 0, 0);
    }
    // T: xt[b] = x[b]^T
    {
        dim3 grid(LX / 32, DDIM / 32, BDIM);
        transpose_x<<<grid, dim3(32, 8, 1)>>>(x, xt);
    }
    // K2: s[b] = y[b] @ xw[b]^T (M=Ly, N=Lx, K=D)
    {
        dim3 grid(LX / GNT, LY / GMT, BDIM);             // (16, 16, 8)
        gemm3xtf32_nt<<<grid, 256, GEMM_SMEM>>>(y, xw, s,
                                                LY, LX, DDIM,
                                                (long long)LY * DDIM,
                                                (long long)LX * DDIM,
                                                (long long)LY * LX);
    }
    // K3: softmax
    softmax_rows<<<BDIM * LY, 256>>>(s);
    // K4: out[b] = s[b] @ xt[b]^T (M=Ly, N=D, K=Lx)
    {
        dim3 grid(DDIM / GNT, LY / GMT, BDIM);           // (4, 16, 8)
        gemm3xtf32_nt<<<grid, 256, GEMM_SMEM>>>(s, xt, out,
                                                LY, DDIM, LX,
                                                (long long)LY * LX,
                                                (long long)DDIM * LX,
                                                (long long)LY * DDIM);
    }
}

// round 17
// speedup vs baseline: 3.8400x; 1.3007x over previous
#include <cuda_runtime.h>
#include <cstdint>
#include <math.h>

// ---------------------------------------------------------------------------
// bilinear_attention: out = softmax(y @ (x @ Wb^T)^T, axis=Lx) @ x
// B=8, Lx=Ly=2048, D=512, fp32 io.
// Round 13: tcgen05 3xTF32 GEMMs; relaxed pipeline redone with ONE MBARRIER
// PER STAGE so the lag-2 wait is a lag-1-phase wait (no parity aliasing —
// the R9 single-barrier version deadlocked on exactly that).
// ---------------------------------------------------------------------------

#define BDIM   8
#define LX     2048
#define LY     2048
#define DDIM   512

__device__ float g_xw[(size_t)BDIM * LX * DDIM];                 // 32 MiB
__device__ float g_s [(size_t)BDIM * (size_t)LY * (size_t)LX];   // 128 MiB
__device__ float g_xt[(size_t)BDIM * DDIM * LX];                 // 32 MiB

// ---- does this compilation pass support tcgen05? --------------------------
#if defined(__CUDA_ARCH__)
#  if defined(__CUDA_ARCH_FEAT_SM103_ALL) || defined(__CUDA_ARCH_FEAT_SM100_ALL) \
      || (defined(__CUDA_ARCH_SPECIFIC__) && (__CUDA_ARCH_SPECIFIC__ >= 1000))   \
      || (defined(__CUDA_ARCH_FAMILY_SPECIFIC__) && (__CUDA_ARCH_FAMILY_SPECIFIC__ >= 1000))
#    define HAS_TCGEN05 1
#  else
#    define HAS_TCGEN05 0
#  endif
#else
#  define HAS_TCGEN05 0
#endif

// ============================ PTX helpers ==================================
__device__ __forceinline__ uint32_t smem_u32(const void* p) {
    uint32_t a;
    asm("{ .reg .u64 t; cvta.to.shared.u64 t, %1; cvt.u32.u64 %0, t; }"
        : "=r"(a) : "l"(p));
    return a;
}

#if HAS_TCGEN05
__device__ __forceinline__ uint32_t elect_one() {
    uint32_t p;
    asm volatile("{\n .reg .pred p;\n elect.sync _|p, 0xFFFFFFFF;\n"
                 " selp.b32 %0, 1, 0, p;\n}" : "=r"(p));
    return p;
}

#define TCGEN05_ALLOC(smem_addr, nCols) \
    asm volatile("tcgen05.alloc.cta_group::1.sync.aligned.shared::cta.b32 [%0], %1;" \
                 :: "r"((uint32_t)(smem_addr)), "r"((uint32_t)(nCols)) : "memory")
#define TCGEN05_DEALLOC(tmem_addr, nCols) \
    asm volatile("tcgen05.dealloc.cta_group::1.sync.aligned.b32 %0, %1;" \
                 :: "r"(tmem_addr), "r"((uint32_t)(nCols)))
#define TCGEN05_RELINQUISH() \
    asm volatile("tcgen05.relinquish_alloc_permit.cta_group::1.sync.aligned;")
#define TCGEN05_COMMIT(mbar) \
    asm volatile("tcgen05.commit.cta_group::1.mbarrier::arrive::one.shared::cluster.b64 [%0];" \
                 :: "r"((uint32_t)(mbar)) : "memory")
#define TCGEN05_FENCE_AFTER() \
    asm volatile("tcgen05.fence::after_thread_sync;" ::: "memory")
#define TCGEN05_FENCE_BEFORE() \
    asm volatile("tcgen05.fence::before_thread_sync;" ::: "memory")
#define TCGEN05_WAIT_LD() \
    asm volatile("tcgen05.wait::ld.sync.aligned;" ::: "memory")
#define FENCE_PROXY_ASYNC() \
    asm volatile("fence.proxy.async.shared::cta;" ::: "memory")

#define MBARRIER_INIT(mbar, cnt) \
    asm volatile("mbarrier.init.shared.b64 [%0], %1;" \
                 :: "r"((uint32_t)(mbar)), "r"((uint32_t)(cnt)) : "memory")
#define MBARRIER_INVAL(mbar) \
    asm volatile("mbarrier.inval.shared.b64 [%0];" :: "r"((uint32_t)(mbar)) : "memory")

#define MBARRIER_WAIT_PARITY(mbar_addr, phase_parity) do {                       \
    uint32_t _mbar = (uint32_t)(mbar_addr);                                      \
    uint32_t _par  = (uint32_t)(phase_parity);                                   \
    uint32_t _done;                                                              \
    asm volatile("{\n .reg .pred p;\n"                                           \
        " mbarrier.try_wait.parity.acquire.cta.shared::cta.b64 p, [%1], %2;\n"   \
        " selp.b32 %0, 1, 0, p;\n}"                                              \
        : "=r"(_done) : "r"(_mbar), "r"(_par) : "memory");                       \
    if (!_done) {                                                                \
        asm volatile("{\n .reg .pred P1;\n"                                      \
            "WL_%=:\n"                                                           \
            " mbarrier.try_wait.parity.acquire.cta.shared::cta.b64 P1, [%0], %1, 0x989680;\n" \
            " @P1 bra.uni WD_%=;\n"                                              \
            " bra.uni WL_%=;\n"                                                  \
            "WD_%=:\n}"                                                          \
            :: "r"(_mbar), "r"(_par) : "memory");                                \
    }                                                                            \
} while (0)

#define TCGEN05_LD_32X32B_X32(r, tmem_addr) \
    asm volatile( \
        "tcgen05.ld.sync.aligned.32x32b.x32.b32 " \
        "{%0, %1, %2, %3, %4, %5, %6, %7, " \
        " %8, %9, %10, %11, %12, %13, %14, %15, " \
        " %16, %17, %18, %19, %20, %21, %22, %23, " \
        " %24, %25, %26, %27, %28, %29, %30, %31}, [%32];" \
        : "=r"((r)[0]),  "=r"((r)[1]),  "=r"((r)[2]),  "=r"((r)[3]), \
          "=r"((r)[4]),  "=r"((r)[5]),  "=r"((r)[6]),  "=r"((r)[7]), \
          "=r"((r)[8]),  "=r"((r)[9]),  "=r"((r)[10]), "=r"((r)[11]), \
          "=r"((r)[12]), "=r"((r)[13]), "=r"((r)[14]), "=r"((r)[15]), \
          "=r"((r)[16]), "=r"((r)[17]), "=r"((r)[18]), "=r"((r)[19]), \
          "=r"((r)[20]), "=r"((r)[21]), "=r"((r)[22]), "=r"((r)[23]), \
          "=r"((r)[24]), "=r"((r)[25]), "=r"((r)[26]), "=r"((r)[27]), \
          "=r"((r)[28]), "=r"((r)[29]), "=r"((r)[30]), "=r"((r)[31]) \
        : "r"(tmem_addr))

// SW128 K-major smem descriptor: layout=2, version=1, SBO=64, LBO=1
static constexpr uint64_t DESC_BASE =
    (uint64_t(2) << 61) | (uint64_t(1) << 46) | (uint64_t(64) << 32) | (uint64_t(1) << 16);
__device__ __forceinline__ uint64_t make_desc(uint32_t addr) {
    return DESC_BASE | ((uint64_t)(addr >> 4) & 0x3FFF);
}

// tcgen05.mma kind::tf32, SS form (both operands via smem descriptor)
__device__ __forceinline__ void mma_tf32_ss(uint32_t d, uint64_t ad, uint64_t bd,
                                            uint32_t idesc, uint32_t enable) {
    asm volatile(
        "{\n .reg .pred p;\n setp.ne.u32 p, %4, 0;\n"
        " tcgen05.mma.cta_group::1.kind::tf32 [%0], %1, %2, %3, p;\n}"
        :: "r"(d), "l"(ad), "l"(bd), "r"(idesc), "r"(enable) : "memory");
}
#endif  // HAS_TCGEN05

__device__ __forceinline__ float tf32_hi(float v) {
    uint32_t u;
    asm("cvt.rna.tf32.f32 %0, %1;" : "=r"(u) : "f"(v));
    return __uint_as_float(u);
}

// ======================= 3xTF32 NT GEMM ====================================
// C[M,N] = A[M,K] * B[N,K]^T, fp32 in/out, split-precision via tf32 hi/lo.
// CTA tile 128x128, K-tile 32 (= one 128B SW128 row; 4 k-steps of K=8).
#define GMT 128
#define GNT 128
#define GKT 32
#define PLANE    16384          // 128 rows * 128B
#define STAGEB   (4 * PLANE)    // Ahi, Alo, Bhi, Blo
#define GEMM_SMEM (2048 + 2 * STAGEB)

#if HAS_TCGEN05
// idesc: dtype F32(1<<4), atype TF32(2<<7), btype TF32(2<<10), N/8<<17, M/16<<24
static constexpr uint32_t IDESC_TF32 =
    (1u << 4) | (2u << 7) | (2u << 10) | ((GNT / 8) << 17) | ((GMT / 16) << 24);

__device__ __forceinline__ void ldg_tile(const float* const* Ap, const float* const* Bp,
                                         int k0, float4* ra, float4* rb)
{
#pragma unroll
    for (int i = 0; i < 4; i++) {
        ra[i] = *(const float4*)(Ap[i] + k0);
        rb[i] = *(const float4*)(Bp[i] + k0);
    }
}

__device__ __forceinline__ void split_store(char* st, const uint32_t* so,
                                            const float4* ra, const float4* rb)
{
#pragma unroll
    for (int i = 0; i < 4; i++) {
        float4 h, l;
        h.x = tf32_hi(ra[i].x); l.x = ra[i].x - h.x;
        h.y = tf32_hi(ra[i].y); l.y = ra[i].y - h.y;
        h.z = tf32_hi(ra[i].z); l.z = ra[i].z - h.z;
        h.w = tf32_hi(ra[i].w); l.w = ra[i].w - h.w;
        *(float4*)(st + so[i])             = h;
        *(float4*)(st + PLANE + so[i])     = l;
        h.x = tf32_hi(rb[i].x); l.x = rb[i].x - h.x;
        h.y = tf32_hi(rb[i].y); l.y = rb[i].y - h.y;
        h.z = tf32_hi(rb[i].z); l.z = rb[i].z - h.z;
        h.w = tf32_hi(rb[i].w); l.w = rb[i].w - h.w;
        *(float4*)(st + 2 * PLANE + so[i]) = h;
        *(float4*)(st + 3 * PLANE + so[i]) = l;
    }
}

// issue the 12 MMAs of one K-tile + commit to the given stage barrier
__device__ __forceinline__ void issue_mma(uint32_t sa, uint32_t tmem,
                                          uint32_t mbar, int first)
{
    FENCE_PROXY_ASYNC();
    if (elect_one()) {
        const uint64_t ah = make_desc(sa);
        const uint64_t al = make_desc(sa + PLANE);
        const uint64_t bh = make_desc(sa + 2 * PLANE);
        const uint64_t bl = make_desc(sa + 3 * PLANE);
#pragma unroll
        for (int ks = 0; ks < 4; ks++) {
            const uint64_t ko = (uint64_t)(ks * 2);   // 32B per k-step
            mma_tf32_ss(tmem, ah + ko, bh + ko, IDESC_TF32,
                        (first && ks == 0) ? 0u : 1u);
            mma_tf32_ss(tmem, ah + ko, bl + ko, IDESC_TF32, 1u);
            mma_tf32_ss(tmem, al + ko, bh + ko, IDESC_TF32, 1u);
        }
        TCGEN05_COMMIT(mbar);
    }
}
#endif  // HAS_TCGEN05

__global__ __launch_bounds__(256, 1)
void gemm3xtf32_nt(const float* __restrict__ A, const float* __restrict__ B,
                   float* __restrict__ C, int M, int N, int K,
                   long long sA, long long sB, long long sC)
{
    extern __shared__ char smem[];
    const int tid = threadIdx.x;
    const int bz  = blockIdx.z;
    A += (long long)bz * sA;
    B += (long long)bz * sB;
    C += (long long)bz * sC;
    const int rowBase = blockIdx.y * GMT;
    const int colBase = blockIdx.x * GNT;

#if HAS_TCGEN05
    // ======================= tcgen05 path ==================================
    const uint32_t base = smem_u32(smem);
    const uint32_t tb   = (base + 32 + 1023) & ~1023u;   // shared-space tile base
    char* tgen = smem + (tb - base);                     // generic-space tile base
    const int wid = tid >> 5, lid = tid & 31;
    // two stage barriers: mbar[s] at base+16+8s. Commit for tile kt ->
    // mbar[kt&1]; that barrier flips once per 2 tiles, so a lag-2-tile wait
    // is a lag-1-phase wait on it -> no parity aliasing, no deadlock.
    const uint32_t mbar0 = base + 16, mbar1 = base + 24;

    if (wid == 0) {
        TCGEN05_ALLOC(base + 0, 128);
        TCGEN05_RELINQUISH();
    }
    if (tid == 0) { MBARRIER_INIT(mbar0, 1); MBARRIER_INIT(mbar1, 1); }
    __syncthreads();
    uint32_t tmem;
    asm volatile("ld.shared.b32 %0, [%1];" : "=r"(tmem) : "r"(base + 0));

    // per-thread load map: 1024 16B-chunks per plane-side, 4 per thread
    int r_[4]; int c4_[4]; uint32_t so_[4];
#pragma unroll
    for (int i = 0; i < 4; i++) {
        int ch = tid + i * 256;
        int r  = ch >> 3, c = ch & 7;
        r_[i] = r; c4_[i] = c * 4;
        uint32_t bo = (uint32_t)(r * 128 + c * 16);
        so_[i] = bo ^ ((bo >> 3) & 0x70);               // SW128 swizzle
    }
    const float* Ap[4]; const float* Bp[4];
#pragma unroll
    for (int i = 0; i < 4; i++) {
        Ap[i] = A + (long long)(rowBase + r_[i]) * K + c4_[i];
        Bp[i] = B + (long long)(colBase + r_[i]) * K + c4_[i];
    }

    const int NKT = K / GKT;                 // 16 or 64 here (even, >= 2)
    float4 raE[4], rbE[4], raO[4], rbO[4];   // ping-pong register tiles

    // prologue: tile0 -> stage0, prefetch tile1 into O set
    ldg_tile(Ap, Bp, 0, raE, rbE);
    split_store(tgen, so_, raE, rbE);
    ldg_tile(Ap, Bp, GKT, raO, rbO);
    __syncthreads();
    if (wid == 0) issue_mma(tb, tmem, mbar0, 1);

    // steady state: iteration kt stores tile kt (regs loaded 1 iter ago),
    // prefetches tile kt+1, and waits only for MMA(kt-2) — the last reader
    // of the stage being overwritten — via that stage's own barrier.
    for (int kt = 1; kt < NKT; ++kt) {
        const int cur = kt & 1;
        char* st = tgen + cur * STAGEB;
        const uint32_t mb = cur ? mbar1 : mbar0;
        if (cur) {
            if (kt + 1 < NKT) ldg_tile(Ap, Bp, (kt + 1) * GKT, raE, rbE);
            if (kt >= 2) MBARRIER_WAIT_PARITY(mb, ((kt - 2) >> 1) & 1);
            split_store(st, so_, raO, rbO);
        } else {
            if (kt + 1 < NKT) ldg_tile(Ap, Bp, (kt + 1) * GKT, raO, rbO);
            MBARRIER_WAIT_PARITY(mb, ((kt - 2) >> 1) & 1);
            split_store(st, so_, raE, rbE);
        }
        __syncthreads();
        if (wid == 0) issue_mma(tb + cur * STAGEB, tmem, mb, 0);
    }
    // drain: last commit on each stage barrier
    {
        const int a = NKT - 2, b = NKT - 1;
        MBARRIER_WAIT_PARITY((a & 1) ? mbar1 : mbar0, (a >> 1) & 1);
        MBARRIER_WAIT_PARITY((b & 1) ? mbar1 : mbar0, (b >> 1) & 1);
    }

    TCGEN05_FENCE_AFTER();
    // epilogue: warps 0-3 read D (128 lanes x 128 fp32 cols) and store
    if (wid < 4) {
        const long long m = rowBase + wid * 32 + lid;
#pragma unroll
        for (int chunk = 0; chunk < 4; chunk++) {
            uint32_t d[32];
            TCGEN05_LD_32X32B_X32(d, tmem + chunk * 32);
            TCGEN05_WAIT_LD();
            float4* dst = (float4*)&C[m * (long long)N + colBase + chunk * 32];
#pragma unroll
            for (int j = 0; j < 8; j++) {
                dst[j] = make_float4(__uint_as_float(d[4 * j + 0]),
                                     __uint_as_float(d[4 * j + 1]),
                                     __uint_as_float(d[4 * j + 2]),
                                     __uint_as_float(d[4 * j + 3]));
            }
        }
        TCGEN05_FENCE_BEFORE();
    }
    __syncthreads();
    if (tid == 0) { MBARRIER_INVAL(mbar0); MBARRIER_INVAL(mbar1); }
    __syncthreads();
    if (wid == 0) {
        TCGEN05_DEALLOC(tmem, 128);
    }

#else
    // ================== FFMA fallback (compute_103 pass) ===================
    const int BKf = 16, TMf = 8, TNf = 8;
    float* As = (float*)smem;                         // [BKf][GMT]
    float* Bs = (float*)(smem + BKf * GMT * 4);       // [BKf][GNT]

    const int tx = tid % (GNT / TNf);                 // 0..15
    const int ty = tid / (GNT / TNf);                 // 0..15

    float acc[TMf][TNf];
#pragma unroll
    for (int i = 0; i < TMf; i++)
#pragma unroll
        for (int j = 0; j < TNf; j++) acc[i][j] = 0.0f;

    for (int k0 = 0; k0 < K; k0 += BKf) {
#pragma unroll
        for (int i = 0; i < (GMT * BKf) / (256 * 4); ++i) {
            int idx = (tid + i * 256) * 4;
            int m = idx / BKf, kk = idx % BKf;
            float4 v = *reinterpret_cast<const float4*>(
                &A[(long long)(rowBase + m) * K + k0 + kk]);
            As[(kk + 0) * GMT + m] = v.x; As[(kk + 1) * GMT + m] = v.y;
            As[(kk + 2) * GMT + m] = v.z; As[(kk + 3) * GMT + m] = v.w;
        }
#pragma unroll
        for (int i = 0; i < (GNT * BKf) / (256 * 4); ++i) {
            int idx = (tid + i * 256) * 4;
            int n = idx / BKf, kk = idx % BKf;
            float4 v = *reinterpret_cast<const float4*>(
                &B[(long long)(colBase + n) * K + k0 + kk]);
            Bs[(kk + 0) * GNT + n] = v.x; Bs[(kk + 1) * GNT + n] = v.y;
            Bs[(kk + 2) * GNT + n] = v.z; Bs[(kk + 3) * GNT + n] = v.w;
        }
        __syncthreads();
#pragma unroll
        for (int kk = 0; kk < BKf; ++kk) {
            float a[TMf], bb[TNf];
#pragma unroll
            for (int i = 0; i < TMf; i++) a[i] = As[kk * GMT + ty * TMf + i];
#pragma unroll
            for (int j = 0; j < TNf; j++) bb[j] = Bs[kk * GNT + tx * TNf + j];
#pragma unroll
            for (int i = 0; i < TMf; i++)
#pragma unroll
                for (int j = 0; j < TNf; j++) acc[i][j] += a[i] * bb[j];
        }
        __syncthreads();
    }
#pragma unroll
    for (int i = 0; i < TMf; i++) {
        long long m = rowBase + ty * TMf + i;
#pragma unroll
        for (int j = 0; j < TNf; j += 4) {
            float4 v = make_float4(acc[i][j], acc[i][j + 1],
                                   acc[i][j + 2], acc[i][j + 3]);
            *reinterpret_cast<float4*>(&C[m * (long long)N + colBase + tx * TNf + j]) = v;
        }
    }
#endif
}

// ===================== transpose: xt[b][d][l] = x[b][l][d] =================
__global__ __launch_bounds__(256)
void transpose_x(const float* __restrict__ x, float* __restrict__ xt)
{
    __shared__ float t[32][33];
    const int b  = blockIdx.z;
    const int l0 = blockIdx.x * 32;
    const int d0 = blockIdx.y * 32;
    const float* xb = x + (long long)b * LX * DDIM;
    float* xtb = xt + (long long)b * DDIM * LX;
    const int tx = threadIdx.x, ty = threadIdx.y;   // 32 x 8
#pragma unroll
    for (int i = 0; i < 32; i += 8)
        t[ty + i][tx] = xb[(long long)(l0 + ty + i) * DDIM + d0 + tx];
    __syncthreads();
#pragma unroll
    for (int i = 0; i < 32; i += 8)
        xtb[(long long)(d0 + ty + i) * LX + l0 + tx] = t[tx][ty + i];
}

// ========================== row softmax ====================================
__global__ __launch_bounds__(256)
void softmax_rows(float* __restrict__ S)
{
    const int N = LX;
    long long row = blockIdx.x;
    float* p = S + row * (long long)N;
    int tid = threadIdx.x;

    float4 v0 = reinterpret_cast<float4*>(p)[tid];
    float4 v1 = reinterpret_cast<float4*>(p)[tid + 256];

    float m = fmaxf(fmaxf(fmaxf(v0.x, v0.y), fmaxf(v0.z, v0.w)),
                    fmaxf(fmaxf(v1.x, v1.y), fmaxf(v1.z, v1.w)));
#pragma unroll
    for (int o = 16; o > 0; o >>= 1)
        m = fmaxf(m, __shfl_xor_sync(0xffffffffu, m, o));

    __shared__ float red[8];
    if ((tid & 31) == 0) red[tid >> 5] = m;
    __syncthreads();
    float mm = red[0];
#pragma unroll
    for (int i = 1; i < 8; i++) mm = fmaxf(mm, red[i]);
    __syncthreads();

    v0.x = expf(v0.x - mm); v0.y = expf(v0.y - mm);
    v0.z = expf(v0.z - mm); v0.w = expf(v0.w - mm);
    v1.x = expf(v1.x - mm); v1.y = expf(v1.y - mm);
    v1.z = expf(v1.z - mm); v1.w = expf(v1.w - mm);

    float s = (v0.x + v0.y + v0.z + v0.w) + (v1.x + v1.y + v1.z + v1.w);
#pragma unroll
    for (int o = 16; o > 0; o >>= 1)
        s += __shfl_xor_sync(0xffffffffu, s, o);
    if ((tid & 31) == 0) red[tid >> 5] = s;
    __syncthreads();
    float total = 0.0f;
#pragma unroll
    for (int i = 0; i < 8; i++) total += red[i];
    float inv = 1.0f / total;

    v0.x *= inv; v0.y *= inv; v0.z *= inv; v0.w *= inv;
    v1.x *= inv; v1.y *= inv; v1.z *= inv; v1.w *= inv;

    reinterpret_cast<float4*>(p)[tid]       = v0;
    reinterpret_cast<float4*>(p)[tid + 256] = v1;
}

// =============================== launch ====================================
extern "C" void kernel_launch(void* const* d_in, const int* in_sizes, int n_in,
                              void* d_out, int out_size)
{
    const float* x  = (const float*)d_in[0];   // [B, Lx, D]
    const float* y  = (const float*)d_in[1];   // [B, Ly, D]
    const float* Wb = (const float*)d_in[2];   // [D, D]
    float* out = (float*)d_out;                // [B, Ly, D]

    float *xw = nullptr, *s = nullptr, *xt = nullptr;
    cudaGetSymbolAddress((void**)&xw, g_xw);
    cudaGetSymbolAddress((void**)&s,  g_s);
    cudaGetSymbolAddress((void**)&xt, g_xt);

    cudaFuncSetAttribute(gemm3xtf32_nt,
                         cudaFuncAttributeMaxDynamicSharedMemorySize, GEMM_SMEM);

    // K1: xw = x @ Wb^T (M=B*Lx=16384, N=512, K=512)
    {
        dim3 grid(DDIM / GNT, (BDIM * LX) / GMT, 1);     // (4, 128, 1)
        gemm3xtf32_nt<<<grid, 256, GEMM_SMEM>>>(x, Wb, xw,
                                                BDIM * LX, DDIM, DDIM, 0, 0, 0);
    }
    // T: xt[b] = x[b]^T
    {
        dim3 grid(LX / 32, DDIM / 32, BDIM);
        transpose_x<<<grid, dim3(32, 8, 1)>>>(x, xt);
    }
    // K2: s[b] = y[b] @ xw[b]^T (M=Ly, N=Lx, K=D)
    {
        dim3 grid(LX / GNT, LY / GMT, BDIM);             // (16, 16, 8)
        gemm3xtf32_nt<<<grid, 256, GEMM_SMEM>>>(y, xw, s,
                                                LY, LX, DDIM,
                                                (long long)LY * DDIM,
                                                (long long)LX * DDIM,
                                                (long long)LY * LX);
    }
    // K3: softmax
    softmax_rows<<<BDIM * LY, 256>>>(s);
    // K4: out[b] = s[b] @ xt[b]^T (M=Ly, N=D, K=Lx)
    {
        dim3 grid(DDIM / GNT, LY / GMT, BDIM);           // (4, 16, 8)
        gemm3xtf32_nt<<<grid, 256, GEMM_SMEM>>>(s, xt, out,
                                                LY, DDIM, LX,
                                                (long long)LY * LX,
                                                (long long)DDIM * LX,
                                                (long long)LY * DDIM);
    }
}